// round 3
// baseline (speedup 1.0000x reference)
#include <cuda_runtime.h>
#include <math.h>

#define B   128
#define L   336
#define N   321
#define E   128
#define LAT 64

__device__ float g_xp[B * N * L];

// -------------------- transpose x [B,L,N] -> xp [B,N,L] --------------------
__global__ void transpose_x(const float* __restrict__ x) {
    __shared__ float tile[32][33];
    const int b  = blockIdx.z;
    const int n0 = blockIdx.x * 32;
    const int l0 = blockIdx.y * 32;
#pragma unroll
    for (int i = 0; i < 32; i += 8) {
        int l = l0 + threadIdx.y + i;
        int n = n0 + threadIdx.x;
        if (l < L && n < N)
            tile[threadIdx.y + i][threadIdx.x] = x[(b * L + l) * N + n];
    }
    __syncthreads();
#pragma unroll
    for (int i = 0; i < 32; i += 8) {
        int n = n0 + threadIdx.y + i;
        int l = l0 + threadIdx.x;
        if (n < N && l < L)
            g_xp[(b * N + n) * L + l] = tile[threadIdx.x][threadIdx.y + i];
    }
}

// -------------------- fused per-channel kernel (v3: 8x8 tiles) ------------
#define BM   64
#define KT   8
#define KT2  16
#define NIT  (L / KT)        // 42
#define HS_LD (E + 4)        // 132 floats per Hs row

// dynamic smem layout (floats):
//   mainloop: As[2][KT][BM] @0 (1024), Bs[2][KT][E] @1024 (2048)
//   phaseB  : Hs[BM][HS_LD] @0 (8448)  -- aliases As/Bs (dead after mainloop)
//   Wm_s[KT2][LAT] @8448 (1024), Wv_s @9472 (1024)
#define SMEM_FLOATS (8448 + 1024 + 1024)

__global__ __launch_bounds__(128, 4) void fused_kernel(
    const float* __restrict__ time_x,
    const float* __restrict__ W_embed,
    const float* __restrict__ b_embed,
    const float* __restrict__ W_mu,
    const float* __restrict__ b_mu,
    const float* __restrict__ W_var,
    const float* __restrict__ b_var,
    float* __restrict__ out)
{
    extern __shared__ float sm[];
    float* AsB = sm;                 // [2][KT][BM]
    float* BsB = sm + 1024;          // [2][KT][E]
    float* Hs  = sm;                 // [BM][HS_LD]
    float* Wm_s = sm + 8448;         // [KT2][LAT]
    float* Wv_s = sm + 9472;         // [KT2][LAT]

    const int n   = blockIdx.x;
    const int b0  = blockIdx.y * BM;
    const int tid = threadIdx.x;
    const int tx  = tid & 15;        // 0..15  (e-groups of 8)
    const int ty  = tid >> 4;        // 0..7   (m-groups of 8)

    float acc[8][8];
#pragma unroll
    for (int i = 0; i < 8; i++)
#pragma unroll
        for (int j = 0; j < 8; j++) acc[i][j] = 0.f;

    const float* Abase = g_xp + ((long)b0 * N + n) * L;
    const float* Bbase = W_embed + (long)n * (L * E);

    // load indices
    const int a_m = tid >> 1;            // 0..63
    const int a_k = (tid & 1) * 4;       // 0 or 4
    const int b_k = tid >> 4;            // 0..7
    const int b_e = (tid & 15) * 8;      // 0..120

    // prologue: stage tile 0
    float4 av  = *(const float4*)(Abase + (long)a_m * (N * L) + a_k);
    float4 bv0 = *(const float4*)(Bbase + b_k * E + b_e);
    float4 bv1 = *(const float4*)(Bbase + b_k * E + b_e + 4);
    AsB[(a_k + 0) * BM + a_m] = av.x;
    AsB[(a_k + 1) * BM + a_m] = av.y;
    AsB[(a_k + 2) * BM + a_m] = av.z;
    AsB[(a_k + 3) * BM + a_m] = av.w;
    *(float4*)&BsB[b_k * E + b_e]     = bv0;
    *(float4*)&BsB[b_k * E + b_e + 4] = bv1;
    __syncthreads();

    for (int it = 0; it < NIT; ++it) {
        const int cur = it & 1;
        float* Asc = AsB + cur * (KT * BM);
        float* Bsc = BsB + cur * (KT * E);
        if (it + 1 < NIT) {              // prefetch next tile into regs
            const int l0 = (it + 1) * KT;
            av  = *(const float4*)(Abase + (long)a_m * (N * L) + l0 + a_k);
            bv0 = *(const float4*)(Bbase + (l0 + b_k) * E + b_e);
            bv1 = *(const float4*)(Bbase + (l0 + b_k) * E + b_e + 4);
        }
#pragma unroll
        for (int k = 0; k < KT; k++) {
            float4 a0 = *(const float4*)&Asc[k * BM + ty * 8];
            float4 a1 = *(const float4*)&Asc[k * BM + ty * 8 + 4];
            float4 q0 = *(const float4*)&Bsc[k * E + tx * 8];
            float4 q1 = *(const float4*)&Bsc[k * E + tx * 8 + 4];
            float a[8]  = {a0.x, a0.y, a0.z, a0.w, a1.x, a1.y, a1.z, a1.w};
            float bb[8] = {q0.x, q0.y, q0.z, q0.w, q1.x, q1.y, q1.z, q1.w};
#pragma unroll
            for (int i = 0; i < 8; i++)
#pragma unroll
                for (int j = 0; j < 8; j++)
                    acc[i][j] += a[i] * bb[j];
        }
        if (it + 1 < NIT) {
            const int nxt = 1 - cur;
            float* Asn = AsB + nxt * (KT * BM);
            float* Bsn = BsB + nxt * (KT * E);
            Asn[(a_k + 0) * BM + a_m] = av.x;
            Asn[(a_k + 1) * BM + a_m] = av.y;
            Asn[(a_k + 2) * BM + a_m] = av.z;
            Asn[(a_k + 3) * BM + a_m] = av.w;
            *(float4*)&Bsn[b_k * E + b_e]     = bv0;
            *(float4*)&Bsn[b_k * E + b_e + 4] = bv1;
            __syncthreads();
        }
    }
    __syncthreads();   // As/Bs dead; Hs region reuse begins

    // ---- epilogue A: bias + sigmoid gate; write h, h_hat; stash h_hat ----
    float* out_h  = out;
    float* out_hh = out + B * N * E;
    const float4 bias_a = *(const float4*)(b_embed + n * E + tx * 8);
    const float4 bias_b = *(const float4*)(b_embed + n * E + tx * 8 + 4);
    const float bias[8] = {bias_a.x, bias_a.y, bias_a.z, bias_a.w,
                           bias_b.x, bias_b.y, bias_b.z, bias_b.w};
#pragma unroll
    for (int i = 0; i < 8; i++) {
        const int m      = ty * 8 + i;
        const int rowoff = (((b0 + m) * N) + n) * E + tx * 8;
        const float4 t_a = *(const float4*)(time_x + rowoff);
        const float4 t_b = *(const float4*)(time_x + rowoff + 4);
        const float t[8] = {t_a.x, t_a.y, t_a.z, t_a.w,
                            t_b.x, t_b.y, t_b.z, t_b.w};
        float h[8], hh[8];
#pragma unroll
        for (int j = 0; j < 8; j++) {
            h[j]  = acc[i][j] + bias[j];
            hh[j] = h[j] / (1.f + __expf(-t[j]));
        }
        *(float4*)(out_h  + rowoff)     = make_float4(h[0], h[1], h[2], h[3]);
        *(float4*)(out_h  + rowoff + 4) = make_float4(h[4], h[5], h[6], h[7]);
        *(float4*)(out_hh + rowoff)     = make_float4(hh[0], hh[1], hh[2], hh[3]);
        *(float4*)(out_hh + rowoff + 4) = make_float4(hh[4], hh[5], hh[6], hh[7]);
        *(float4*)&Hs[m * HS_LD + tx * 8]     = make_float4(hh[0], hh[1], hh[2], hh[3]);
        *(float4*)&Hs[m * HS_LD + tx * 8 + 4] = make_float4(hh[4], hh[5], hh[6], hh[7]);
    }
    __syncthreads();

    // ---- phase B: mu / var ----
    // thread computes rows m=ty*8..+8, lat cols tx*4..+4 for both mu and var
    float accm[8][4], accv[8][4];
#pragma unroll
    for (int i = 0; i < 8; i++)
#pragma unroll
        for (int j = 0; j < 4; j++) { accm[i][j] = 0.f; accv[i][j] = 0.f; }

    const float* Wm = W_mu  + (long)n * (E * LAT);
    const float* Wv = W_var + (long)n * (E * LAT);
    const int w_e = tid >> 4;         // 0..7 (rows, +8 for second half)
    const int w_k = (tid & 15) * 4;   // 0..60

    for (int e0 = 0; e0 < E; e0 += KT2) {
        *(float4*)&Wm_s[(w_e    ) * LAT + w_k] = *(const float4*)(Wm + (e0 + w_e    ) * LAT + w_k);
        *(float4*)&Wm_s[(w_e + 8) * LAT + w_k] = *(const float4*)(Wm + (e0 + w_e + 8) * LAT + w_k);
        *(float4*)&Wv_s[(w_e    ) * LAT + w_k] = *(const float4*)(Wv + (e0 + w_e    ) * LAT + w_k);
        *(float4*)&Wv_s[(w_e + 8) * LAT + w_k] = *(const float4*)(Wv + (e0 + w_e + 8) * LAT + w_k);
        __syncthreads();
#pragma unroll
        for (int ke = 0; ke < KT2; ke++) {
            const int e = e0 + ke;
            float a[8];
#pragma unroll
            for (int i = 0; i < 8; i++) a[i] = Hs[(ty * 8 + i) * HS_LD + e];
            const float4 wm4 = *(const float4*)&Wm_s[ke * LAT + tx * 4];
            const float4 wv4 = *(const float4*)&Wv_s[ke * LAT + tx * 4];
            const float wm[4] = {wm4.x, wm4.y, wm4.z, wm4.w};
            const float wv[4] = {wv4.x, wv4.y, wv4.z, wv4.w};
#pragma unroll
            for (int i = 0; i < 8; i++)
#pragma unroll
                for (int j = 0; j < 4; j++) {
                    accm[i][j] += a[i] * wm[j];
                    accv[i][j] += a[i] * wv[j];
                }
        }
        __syncthreads();
    }

    float* out_mu  = out + 2 * B * N * E;
    float* out_var = out_mu + B * N * LAT;
    const float4 bm4 = *(const float4*)(b_mu  + n * LAT + tx * 4);
    const float4 bv4 = *(const float4*)(b_var + n * LAT + tx * 4);
#pragma unroll
    for (int i = 0; i < 8; i++) {
        const int m   = ty * 8 + i;
        const int off = (((b0 + m) * N) + n) * LAT + tx * 4;
        *(float4*)(out_mu + off) = make_float4(accm[i][0] + bm4.x, accm[i][1] + bm4.y,
                                               accm[i][2] + bm4.z, accm[i][3] + bm4.w);
        *(float4*)(out_var + off) = make_float4(accv[i][0] + bv4.x, accv[i][1] + bv4.y,
                                                accv[i][2] + bv4.z, accv[i][3] + bv4.w);
    }
}

extern "C" void kernel_launch(void* const* d_in, const int* in_sizes, int n_in,
                              void* d_out, int out_size) {
    const float* x       = (const float*)d_in[0];
    const float* time_x  = (const float*)d_in[1];
    const float* W_embed = (const float*)d_in[2];
    const float* b_embed = (const float*)d_in[3];
    const float* W_mu    = (const float*)d_in[4];
    const float* b_mu    = (const float*)d_in[5];
    const float* W_var   = (const float*)d_in[6];
    const float* b_var   = (const float*)d_in[7];
    float* out = (float*)d_out;

    dim3 tgrid((N + 31) / 32, (L + 31) / 32, B);
    dim3 tblock(32, 8);
    transpose_x<<<tgrid, tblock>>>(x);

    static const int smem_bytes = SMEM_FLOATS * 4;
    cudaFuncSetAttribute(fused_kernel,
                         cudaFuncAttributeMaxDynamicSharedMemorySize, smem_bytes);
    dim3 ggrid(N, B / BM);
    fused_kernel<<<ggrid, 128, smem_bytes>>>(time_x, W_embed, b_embed,
                                             W_mu, b_mu, W_var, b_var, out);
}

// round 6
// speedup vs baseline: 1.6448x; 1.6448x over previous
#include <cuda_runtime.h>
#include <math.h>
#include <stdint.h>

#define Bq   128
#define Lq   336
#define Nq   321
#define Eq   128
#define LATq 64

#define KC    16
#define NST1  (Lq / KC)   // 21
#define NST2  (Eq / KC)   // 8

__device__ __align__(1024) float g_xp[Bq * Nq * Lq];   // x -> [B][N][L]

// ---------------- transpose x [B,L,N] -> [B,N,L] ----------------
__global__ void transpose_x(const float* __restrict__ x) {
    __shared__ float tile[32][33];
    const int b  = blockIdx.z;
    const int n0 = blockIdx.x * 32;
    const int l0 = blockIdx.y * 32;
#pragma unroll
    for (int i = 0; i < 32; i += 8) {
        int l = l0 + threadIdx.y + i;
        int n = n0 + threadIdx.x;
        if (l < Lq && n < Nq)
            tile[threadIdx.y + i][threadIdx.x] = x[((size_t)b * Lq + l) * Nq + n];
    }
    __syncthreads();
#pragma unroll
    for (int i = 0; i < 32; i += 8) {
        int n = n0 + threadIdx.y + i;
        int l = l0 + threadIdx.x;
        if (n < Nq && l < Lq)
            g_xp[((size_t)b * Nq + n) * Lq + l] = tile[threadIdx.x][threadIdx.y + i];
    }
}

// ---------------- helpers ----------------
__device__ __forceinline__ uint32_t smem_u32(const void* p) {
    uint32_t a;
    asm("{ .reg .u64 t; cvta.to.shared.u64 t, %1; cvt.u32.u64 %0, t; }" : "=r"(a) : "l"(p));
    return a;
}
__device__ __forceinline__ float rna(float x) {
    uint32_t u; asm("cvt.rna.tf32.f32 %0, %1;" : "=r"(u) : "f"(x));
    return __uint_as_float(u);
}

#define LDSM_X4(r0, r1, r2, r3, addr)                                          \
    asm volatile("ldmatrix.sync.aligned.m8n8.x4.shared.b16 {%0,%1,%2,%3}, [%4];" \
        : "=r"(r0), "=r"(r1), "=r"(r2), "=r"(r3) : "r"(addr))

#define MMA_TF32(c, a, b0v, b1v)                                               \
    asm volatile("mma.sync.aligned.m16n8k8.row.col.f32.tf32.tf32.f32 "         \
        "{%0,%1,%2,%3},{%4,%5,%6,%7},{%8,%9},{%0,%1,%2,%3};"                   \
        : "+f"((c)[0]), "+f"((c)[1]), "+f"((c)[2]), "+f"((c)[3])               \
        : "r"((a)[0]), "r"((a)[1]), "r"((a)[2]), "r"((a)[3]),                  \
          "r"(b0v), "r"(b1v))

// smem float-offsets
#define AS_F(s)  ((s) * 1280)            // [2][64][20]
#define BS_F(s)  (2560 + (s) * 2560)     // [2][128][20]
#define BS2_F(s) ((s) * 2560)            // alias over As/Bs
#define HS_F     7680                    // [64][132]
#define SMEM_F   16128                   // 64512 bytes

// ---------------- fused grouped GEMM (tf32 mma.sync) ----------------
__global__ __launch_bounds__(128, 3) void gemm_kernel(
    const float* __restrict__ W_embed,
    const float* __restrict__ b_embed,
    const float* __restrict__ W_mu,
    const float* __restrict__ b_mu,
    const float* __restrict__ W_var,
    const float* __restrict__ b_var,
    const float* __restrict__ time_x,
    float* __restrict__ out)
{
    extern __shared__ float smf[];
    const uint32_t sb = smem_u32(smf);

    const int tid  = threadIdx.x;
    const int lane = tid & 31;
    const int wid  = tid >> 5;
    const int wm   = wid & 1;            // warp row   (2 x 32 m-rows)
    const int wn   = wid >> 1;           // warp col   (2 x 64 n-cols)
    const int n    = blockIdx.y;
    const int b0   = blockIdx.x * 64;

    const int lr  = lane & 7;
    const int lm  = lane >> 3;
    const int gid = lane >> 2;
    const int tig = lane & 3;

    // ldmatrix lane geometry
    const int arow  = wm * 32 + ((lm & 1) << 3) + lr;     // + i*16
    const int akoff = (lm >> 1) << 4;                     // bytes; + ks*32
    const int brow  = wn * 64 + ((lm >> 1) << 3) + lr;    // + j2*16
    const int bkoff = (lm & 1) << 4;                      // bytes; + ks*32

    // ---------------- GEMM1: h = xp @ W_embed ----------------
    float c[2][8][4];
#pragma unroll
    for (int i = 0; i < 2; i++)
#pragma unroll
        for (int j = 0; j < 8; j++)
#pragma unroll
            for (int q = 0; q < 4; q++) c[i][j][q] = 0.f;

    // staging indices
    const int a_row = (tid >> 2) & 63;        // via idx = tid + i*128
    const int a_kq  = tid & 3;
    const float* Ag0 = g_xp + ((size_t)(b0 + a_row) * Nq + n) * Lq + a_kq * 4;
    const float* Ag1 = g_xp + ((size_t)(b0 + a_row + 32) * Nq + n) * Lq + a_kq * 4;
    const float* Wg  = W_embed + (size_t)n * Lq * Eq;

    float4 wa[2], wb[4];
    {   // prologue: stage 0
        wa[0] = *(const float4*)(Ag0);
        wa[1] = *(const float4*)(Ag1);
#pragma unroll
        for (int i = 0; i < 4; i++) {
            const int idx = tid + i * 128;
            const int lrow = idx & 15, e0 = (idx >> 4) * 4;
            wb[i] = *(const float4*)(Wg + (size_t)lrow * Eq + e0);
        }
        float* As = smf + AS_F(0) + a_row * 20 + a_kq * 4;
        As[0] = rna(wa[0].x); As[1] = rna(wa[0].y); As[2] = rna(wa[0].z); As[3] = rna(wa[0].w);
        float* As2 = smf + AS_F(0) + (a_row + 32) * 20 + a_kq * 4;
        As2[0] = rna(wa[1].x); As2[1] = rna(wa[1].y); As2[2] = rna(wa[1].z); As2[3] = rna(wa[1].w);
#pragma unroll
        for (int i = 0; i < 4; i++) {
            const int idx = tid + i * 128;
            const int lrow = idx & 15, e0 = (idx >> 4) * 4;
            float* Bs = smf + BS_F(0);
            Bs[(e0 + 0) * 20 + lrow] = rna(wb[i].x);
            Bs[(e0 + 1) * 20 + lrow] = rna(wb[i].y);
            Bs[(e0 + 2) * 20 + lrow] = rna(wb[i].z);
            Bs[(e0 + 3) * 20 + lrow] = rna(wb[i].w);
        }
    }
    __syncthreads();

    for (int st = 0; st < NST1; ++st) {
        const int cur = st & 1;
        if (st + 1 < NST1) {
            const int l0 = (st + 1) * KC;
            wa[0] = *(const float4*)(Ag0 + l0);
            wa[1] = *(const float4*)(Ag1 + l0);
#pragma unroll
            for (int i = 0; i < 4; i++) {
                const int idx = tid + i * 128;
                const int lrow = idx & 15, e0 = (idx >> 4) * 4;
                wb[i] = *(const float4*)(Wg + (size_t)(l0 + lrow) * Eq + e0);
            }
        }
        const uint32_t asb = sb + (AS_F(cur)) * 4;
        const uint32_t bsb = sb + (BS_F(cur)) * 4;
#pragma unroll
        for (int ks = 0; ks < 2; ks++) {
            uint32_t a[2][4], bb[4][4];
#pragma unroll
            for (int i = 0; i < 2; i++)
                LDSM_X4(a[i][0], a[i][1], a[i][2], a[i][3],
                        asb + (uint32_t)(arow + i * 16) * 80 + akoff + ks * 32);
#pragma unroll
            for (int j2 = 0; j2 < 4; j2++)
                LDSM_X4(bb[j2][0], bb[j2][1], bb[j2][2], bb[j2][3],
                        bsb + (uint32_t)(brow + j2 * 16) * 80 + bkoff + ks * 32);
#pragma unroll
            for (int i = 0; i < 2; i++)
#pragma unroll
                for (int j = 0; j < 8; j++)
                    MMA_TF32(c[i][j], a[i], bb[j >> 1][(j & 1) * 2], bb[j >> 1][(j & 1) * 2 + 1]);
        }
        if (st + 1 < NST1) {
            const int nxt = 1 - cur;
            float* As = smf + AS_F(nxt) + a_row * 20 + a_kq * 4;
            As[0] = rna(wa[0].x); As[1] = rna(wa[0].y); As[2] = rna(wa[0].z); As[3] = rna(wa[0].w);
            float* As2 = smf + AS_F(nxt) + (a_row + 32) * 20 + a_kq * 4;
            As2[0] = rna(wa[1].x); As2[1] = rna(wa[1].y); As2[2] = rna(wa[1].z); As2[3] = rna(wa[1].w);
#pragma unroll
            for (int i = 0; i < 4; i++) {
                const int idx = tid + i * 128;
                const int lrow = idx & 15, e0 = (idx >> 4) * 4;
                float* Bs = smf + BS_F(nxt);
                Bs[(e0 + 0) * 20 + lrow] = rna(wb[i].x);
                Bs[(e0 + 1) * 20 + lrow] = rna(wb[i].y);
                Bs[(e0 + 2) * 20 + lrow] = rna(wb[i].z);
                Bs[(e0 + 3) * 20 + lrow] = rna(wb[i].w);
            }
            __syncthreads();
        }
    }

    // prefetch GEMM2 stage-0 weights (into regs) before epilogue
    const float* Mg = W_mu  + (size_t)n * Eq * LATq;
    const float* Vg = W_var + (size_t)n * Eq * LATq;
    float4 w2[4];
    {
        const int idx = tid, lrow = idx & 15, lat0 = (idx >> 4) * 4;
        const int idx1 = tid + 128, lrow1 = idx1 & 15, lat1 = ((idx1 >> 4) & 15) * 4;
        w2[0] = *(const float4*)(Mg + (size_t)lrow  * LATq + lat0);
        w2[1] = *(const float4*)(Mg + (size_t)lrow1 * LATq + lat1);
        w2[2] = *(const float4*)(Vg + (size_t)lrow  * LATq + lat0);
        w2[3] = *(const float4*)(Vg + (size_t)lrow1 * LATq + lat1);
    }

    // ---------------- epilogue 1: bias + sigmoid gate ----------------
    float* out_h  = out;
    float* out_hh = out + Bq * Nq * Eq;
#pragma unroll
    for (int j = 0; j < 8; j++) {
        const int e = wn * 64 + j * 8 + tig * 2;
        const float2 be = *(const float2*)(b_embed + n * Eq + e);
#pragma unroll
        for (int i = 0; i < 2; i++) {
#pragma unroll
            for (int half = 0; half < 2; half++) {
                const int m = wm * 32 + i * 16 + gid + half * 8;
                const size_t ro = ((size_t)(b0 + m) * Nq + n) * Eq + e;
                const float2 t2 = *(const float2*)(time_x + ro);
                const float h0 = c[i][j][half * 2]     + be.x;
                const float h1 = c[i][j][half * 2 + 1] + be.y;
                const float hh0 = h0 / (1.f + __expf(-t2.x));
                const float hh1 = h1 / (1.f + __expf(-t2.y));
                *(float2*)(out_h  + ro) = make_float2(h0, h1);
                *(float2*)(out_hh + ro) = make_float2(hh0, hh1);
                *(float2*)(smf + HS_F + m * 132 + e) = make_float2(rna(hh0), rna(hh1));
            }
        }
    }
    __syncthreads();   // Hs visible; As/Bs dead -> Bs2 alias safe

    // stage 0 of GEMM2 weights
    {
        const int idx = tid, lrow = idx & 15, lat0 = (idx >> 4) * 4;
        const int idx1 = tid + 128, lrow1 = idx1 & 15, lat1 = ((idx1 >> 4) & 15) * 4;
        float* Bs2 = smf + BS2_F(0);
        Bs2[(lat0 + 0) * 20 + lrow] = rna(w2[0].x);
        Bs2[(lat0 + 1) * 20 + lrow] = rna(w2[0].y);
        Bs2[(lat0 + 2) * 20 + lrow] = rna(w2[0].z);
        Bs2[(lat0 + 3) * 20 + lrow] = rna(w2[0].w);
        Bs2[(lat1 + 0) * 20 + lrow1] = rna(w2[1].x);
        Bs2[(lat1 + 1) * 20 + lrow1] = rna(w2[1].y);
        Bs2[(lat1 + 2) * 20 + lrow1] = rna(w2[1].z);
        Bs2[(lat1 + 3) * 20 + lrow1] = rna(w2[1].w);
        Bs2[(64 + lat0 + 0) * 20 + lrow] = rna(w2[2].x);
        Bs2[(64 + lat0 + 1) * 20 + lrow] = rna(w2[2].y);
        Bs2[(64 + lat0 + 2) * 20 + lrow] = rna(w2[2].z);
        Bs2[(64 + lat0 + 3) * 20 + lrow] = rna(w2[2].w);
        Bs2[(64 + lat1 + 0) * 20 + lrow1] = rna(w2[3].x);
        Bs2[(64 + lat1 + 1) * 20 + lrow1] = rna(w2[3].y);
        Bs2[(64 + lat1 + 2) * 20 + lrow1] = rna(w2[3].z);
        Bs2[(64 + lat1 + 3) * 20 + lrow1] = rna(w2[3].w);
    }
    __syncthreads();

    // ---------------- GEMM2: [mu | var] = h_hat @ [W_mu | W_var] --------
#pragma unroll
    for (int i = 0; i < 2; i++)
#pragma unroll
        for (int j = 0; j < 8; j++)
#pragma unroll
            for (int q = 0; q < 4; q++) c[i][j][q] = 0.f;

    for (int st = 0; st < NST2; ++st) {
        const int cur = st & 1;
        if (st + 1 < NST2) {
            const int e0 = (st + 1) * KC;
            const int idx = tid, lrow = idx & 15, lat0 = (idx >> 4) * 4;
            const int idx1 = tid + 128, lrow1 = idx1 & 15, lat1 = ((idx1 >> 4) & 15) * 4;
            w2[0] = *(const float4*)(Mg + (size_t)(e0 + lrow)  * LATq + lat0);
            w2[1] = *(const float4*)(Mg + (size_t)(e0 + lrow1) * LATq + lat1);
            w2[2] = *(const float4*)(Vg + (size_t)(e0 + lrow)  * LATq + lat0);
            w2[3] = *(const float4*)(Vg + (size_t)(e0 + lrow1) * LATq + lat1);
        }
        const uint32_t hsb = sb + HS_F * 4;
        const uint32_t b2b = sb + BS2_F(cur) * 4;
#pragma unroll
        for (int ks = 0; ks < 2; ks++) {
            uint32_t a[2][4], bb[4][4];
#pragma unroll
            for (int i = 0; i < 2; i++)
                LDSM_X4(a[i][0], a[i][1], a[i][2], a[i][3],
                        hsb + (uint32_t)(arow + i * 16) * 528 + akoff + st * 64 + ks * 32);
#pragma unroll
            for (int j2 = 0; j2 < 4; j2++)
                LDSM_X4(bb[j2][0], bb[j2][1], bb[j2][2], bb[j2][3],
                        b2b + (uint32_t)(brow + j2 * 16) * 80 + bkoff + ks * 32);
#pragma unroll
            for (int i = 0; i < 2; i++)
#pragma unroll
                for (int j = 0; j < 8; j++)
                    MMA_TF32(c[i][j], a[i], bb[j >> 1][(j & 1) * 2], bb[j >> 1][(j & 1) * 2 + 1]);
        }
        if (st + 1 < NST2) {
            const int nxt = 1 - cur;
            const int idx = tid, lrow = idx & 15, lat0 = (idx >> 4) * 4;
            const int idx1 = tid + 128, lrow1 = idx1 & 15, lat1 = ((idx1 >> 4) & 15) * 4;
            float* Bs2 = smf + BS2_F(nxt);
            Bs2[(lat0 + 0) * 20 + lrow] = rna(w2[0].x);
            Bs2[(lat0 + 1) * 20 + lrow] = rna(w2[0].y);
            Bs2[(lat0 + 2) * 20 + lrow] = rna(w2[0].z);
            Bs2[(lat0 + 3) * 20 + lrow] = rna(w2[0].w);
            Bs2[(lat1 + 0) * 20 + lrow1] = rna(w2[1].x);
            Bs2[(lat1 + 1) * 20 + lrow1] = rna(w2[1].y);
            Bs2[(lat1 + 2) * 20 + lrow1] = rna(w2[1].z);
            Bs2[(lat1 + 3) * 20 + lrow1] = rna(w2[1].w);
            Bs2[(64 + lat0 + 0) * 20 + lrow] = rna(w2[2].x);
            Bs2[(64 + lat0 + 1) * 20 + lrow] = rna(w2[2].y);
            Bs2[(64 + lat0 + 2) * 20 + lrow] = rna(w2[2].z);
            Bs2[(64 + lat0 + 3) * 20 + lrow] = rna(w2[2].w);
            Bs2[(64 + lat1 + 0) * 20 + lrow1] = rna(w2[3].x);
            Bs2[(64 + lat1 + 1) * 20 + lrow1] = rna(w2[3].y);
            Bs2[(64 + lat1 + 2) * 20 + lrow1] = rna(w2[3].z);
            Bs2[(64 + lat1 + 3) * 20 + lrow1] = rna(w2[3].w);
            __syncthreads();
        }
    }

    // ---------------- epilogue 2 ----------------
    float* out_mu  = out + 2 * Bq * Nq * Eq;
    float* out_var = out_mu + Bq * Nq * LATq;
    float* dst = wn ? out_var : out_mu;
    const float* bias = (wn ? b_var : b_mu) + n * LATq;
#pragma unroll
    for (int j = 0; j < 8; j++) {
        const int col = j * 8 + tig * 2;
        const float2 bb2 = *(const float2*)(bias + col);
#pragma unroll
        for (int i = 0; i < 2; i++) {
#pragma unroll
            for (int half = 0; half < 2; half++) {
                const int m = wm * 32 + i * 16 + gid + half * 8;
                const size_t off = ((size_t)(b0 + m) * Nq + n) * LATq + col;
                *(float2*)(dst + off) = make_float2(c[i][j][half * 2] + bb2.x,
                                                    c[i][j][half * 2 + 1] + bb2.y);
            }
        }
    }
}

// ---------------- host ----------------
extern "C" void kernel_launch(void* const* d_in, const int* in_sizes, int n_in,
                              void* d_out, int out_size) {
    const float* x       = (const float*)d_in[0];
    const float* time_x  = (const float*)d_in[1];
    const float* W_embed = (const float*)d_in[2];
    const float* b_embed = (const float*)d_in[3];
    const float* W_mu    = (const float*)d_in[4];
    const float* b_mu    = (const float*)d_in[5];
    const float* W_var   = (const float*)d_in[6];
    const float* b_var   = (const float*)d_in[7];
    float* out = (float*)d_out;

    dim3 tgrid((Nq + 31) / 32, (Lq + 31) / 32, Bq);
    dim3 tblock(32, 8);
    transpose_x<<<tgrid, tblock>>>(x);

    const int smem_bytes = SMEM_F * 4;
    cudaFuncSetAttribute(gemm_kernel,
                         cudaFuncAttributeMaxDynamicSharedMemorySize, smem_bytes);
    dim3 ggrid(2, Nq);
    gemm_kernel<<<ggrid, 128, smem_bytes>>>(W_embed, b_embed, W_mu, b_mu,
                                            W_var, b_var, time_x, out);
}